// round 4
// baseline (speedup 1.0000x reference)
#include <cuda_runtime.h>

#define BATCH 32
#define HH 1024
#define WW 1024
#define WPR 32
#define NCELLS (BATCH * HH * WW)

#define TH 64          // interior rows per tile
#define SH (TH + 16)   // 80 smem rows (8-row halo each side)
#define SW 34          // 32 data word cols + 2 zero guard cols
#define NTILES (BATCH * (HH / TH))   // 512

__device__ unsigned long long g_live;
__device__ unsigned long long g_mism;
__device__ unsigned g_done;

__device__ __forceinline__ void hsum(unsigned l, unsigned m, unsigned r,
                                     unsigned& h0, unsigned& h1) {
    unsigned L = __funnelshift_l(l, m, 1);
    unsigned R = __funnelshift_r(m, r, 1);
    unsigned t = L ^ R;
    h0 = t ^ m;
    h1 = (L & R) | (t & m);
}

__device__ __forceinline__ unsigned gol_combine(
    unsigned h0a, unsigned h1a, unsigned h0b, unsigned h1b,
    unsigned h0c, unsigned h1c, unsigned bm) {
    unsigned t  = h0a ^ h0b;
    unsigned s0 = t ^ h0c;
    unsigned c1 = (h0a & h0b) | (t & h0c);
    unsigned u  = h1a ^ h1b;
    unsigned p  = u ^ h1c;
    unsigned q  = (h1a & h1b) | (u & h1c);
    unsigned s1 = p ^ c1;
    unsigned c2 = p & c1;
    unsigned eq3 = s0 & s1 & ~(q | c2);       // total == 3
    unsigned eq4 = (q ^ c2) & ~(s0 | s1);     // total == 4
    return eq3 | (bm & eq4);
}

__global__ __launch_bounds__(256) void k_gol(const float* __restrict__ ini,
                                             const float* __restrict__ tgt,
                                             float* __restrict__ out) {
    __shared__ unsigned sb[2][SH][SW];   // ping-pong life tiles
    __shared__ unsigned st[TH][WPR];     // packed target bits (interior)
    __shared__ int sh_live[8], sh_mism[8];

    int tile = blockIdx.x;
    int b    = tile >> 4;
    int ty   = tile & 15;
    int r0   = ty * TH;
    int tid  = threadIdx.x;
    int lane = tid & 31;
    int wrp  = tid >> 5;

    // zero guard columns
    for (int s = tid; s < SH; s += 256) {
        sb[0][s][0] = 0u; sb[0][s][33] = 0u;
        sb[1][s][0] = 0u; sb[1][s][33] = 0u;
    }

    // ---- pack initial tile + halo directly from float input ----
    const float* inib = ini + (size_t)b * HH * WW;
    for (int i = tid; i < SH * 256; i += 256) {       // 256 float4 per row
        int s = i >> 8;
        int q = i & 255;                              // float4 index in row
        int gr = r0 - 8 + s;
        unsigned nib = 0u;
        if ((unsigned)gr < (unsigned)HH) {
            float4 f = ((const float4*)(inib + (size_t)gr * WW))[q];
            nib = (f.x > 0.5f ? 1u : 0u) | (f.y > 0.5f ? 2u : 0u)
                | (f.z > 0.5f ? 4u : 0u) | (f.w > 0.5f ? 8u : 0u);
        }
        unsigned v = nib << ((lane & 7) * 4);
        v |= __shfl_xor_sync(0xffffffffu, v, 1);
        v |= __shfl_xor_sync(0xffffffffu, v, 2);
        v |= __shfl_xor_sync(0xffffffffu, v, 4);
        if ((lane & 7) == 0) sb[0][s][(q >> 3) + 1] = v;   // q>>3 groups of 8 lanes
    }
    __syncthreads();

    const float* tgtb = tgt + ((size_t)b * HH + r0) * WW;
    float* outs = out + 1 + ((size_t)b * HH + r0) * WW;            // state tile
    float* outt = out + 1 + (size_t)NCELLS + ((size_t)b * HH + r0) * WW; // target tile

    int c      = tid & 31;
    int strip  = tid >> 5;
    int rstart = 1 + strip * 10;
    int rend   = (rstart + 10 < 79) ? (rstart + 10) : 79;

    #pragma unroll
    for (int g = 0; g < 8; ++g) {
        int cur = g & 1, nxt = cur ^ 1;

        // ---- interleaved target copy+pack: 1/8 of tile per generation ----
        // Overlaps this DRAM traffic with the sim's ALU work.
        {
            int base = g * 8192;                       // 8 rows of the tile
            #pragma unroll 8
            for (int k = 0; k < 32; ++k) {
                int i = base + k * 256 + tid;
                float f = tgtb[i];
                outt[i] = f;
                unsigned bb = __ballot_sync(0xffffffffu, f > 0.5f);
                if (lane == 0) st[i >> 10][(i & 1023) >> 5] = bb;
            }
        }

        // ---- one bit-sliced generation ----
        unsigned h0a, h1a, h0b, h1b, h0c, h1c;
        hsum(sb[cur][rstart - 1][c], sb[cur][rstart - 1][c + 1], sb[cur][rstart - 1][c + 2], h0a, h1a);
        unsigned bm = sb[cur][rstart][c + 1];
        hsum(sb[cur][rstart][c], bm, sb[cur][rstart][c + 2], h0b, h1b);

        for (int r = rstart; r < rend; ++r) {
            unsigned nl = sb[cur][r + 1][c];
            unsigned nm = sb[cur][r + 1][c + 1];
            unsigned nr = sb[cur][r + 1][c + 2];
            hsum(nl, nm, nr, h0c, h1c);

            unsigned next = gol_combine(h0a, h1a, h0b, h1b, h0c, h1c, bm);
            if ((unsigned)(r0 - 8 + r) >= (unsigned)HH) next = 0u;  // keep outside zero
            sb[nxt][r][c + 1] = next;

            h0a = h0b; h1a = h1b;
            h0b = h0c; h1b = h1c;
            bm  = nm;
        }
        __syncthreads();
    }
    // final state: sb[0], interior smem rows [8, 72); target bits in st[][]

    // ---- word-level live / mismatch counts ----
    int live = 0, mism = 0;
    #pragma unroll
    for (int k = 0; k < 8; ++k) {
        int widx = tid + 256 * k;                  // 0..2047
        int row  = widx >> 5, col = widx & 31;
        unsigned w = sb[0][8 + row][col + 1];
        live += __popc(w);
        mism += __popc(w ^ st[row][col]);
    }

    // ---- state float expansion (coalesced STG.32, LDS broadcast) ----
    #pragma unroll 4
    for (int i = tid; i < TH * 1024; i += 256) {
        int row = i >> 10;
        int wc  = (i & 1023) >> 5;                 // uniform per warp
        unsigned w = sb[0][8 + row][wc + 1];
        outs[i] = __uint_as_float(((w >> lane) & 1u) * 0x3f800000u);
    }

    // ---- block reduce + global atomics + last-block finalize/self-reset ----
    #pragma unroll
    for (int o = 16; o > 0; o >>= 1) {
        live += __shfl_down_sync(0xffffffffu, live, o);
        mism += __shfl_down_sync(0xffffffffu, mism, o);
    }
    if (lane == 0) { sh_live[wrp] = live; sh_mism[wrp] = mism; }
    __syncthreads();
    if (tid == 0) {
        int L = 0, M = 0;
        #pragma unroll
        for (int k = 0; k < 8; ++k) { L += sh_live[k]; M += sh_mism[k]; }
        atomicAdd(&g_live, (unsigned long long)L);
        atomicAdd(&g_mism, (unsigned long long)M);
        __threadfence();
        unsigned prev = atomicAdd(&g_done, 1u);
        if (prev == (unsigned)(gridDim.x - 1)) {
            // all blocks' atomics are visible (done-counter + fence ordering)
            unsigned long long mt = atomicAdd(&g_mism, 0ull);
            unsigned long long lt = atomicAdd(&g_live, 0ull);
            out[0]              = (float)((double)mt / (double)NCELLS);  // loss
            out[1 + 2 * NCELLS] = (float)lt;                             // live_cells
            out[2 + 2 * NCELLS] = mt ? 1.0f : 0.0f;                      // max_abs_error
            // self-reset for next graph replay (deterministic: only last block)
            g_live = 0ull; g_mism = 0ull;
            __threadfence();
            g_done = 0u;
        }
    }
}

extern "C" void kernel_launch(void* const* d_in, const int* in_sizes, int n_in,
                              void* d_out, int out_size) {
    const float* initial = (const float*)d_in[0];
    const float* target  = (const float*)d_in[1];
    (void)in_sizes; (void)n_in; (void)out_size;   // generations fixed at 8

    k_gol<<<NTILES, 256>>>(initial, target, (float*)d_out);
}

// round 5
// speedup vs baseline: 1.2948x; 1.2948x over previous
#include <cuda_runtime.h>

#define BATCH 32
#define HH 1024
#define WW 1024
#define WPR 32
#define WORDS_PER_IMG (HH * WPR)
#define NWORDS (BATCH * WORDS_PER_IMG)   // 1048576
#define NCELLS (BATCH * HH * WW)         // 33554432

#define TH 64
#define SH (TH + 16)
#define SW 34
#define SIMB (BATCH * (HH / TH))         // 512 sim blocks

__device__ unsigned g_A[NWORDS];
__device__ unsigned g_B[NWORDS];
__device__ unsigned g_T[NWORDS];
__device__ unsigned long long g_live;
__device__ unsigned long long g_mism;
__device__ unsigned g_done;

// ---------------------------------------------------------------------------
// K1: pack initial state floats -> bits. Warp: 256 cells, MLP-8 loads.
// ---------------------------------------------------------------------------
__global__ void k_pack_ini(const float* __restrict__ ini) {
    int tid  = blockIdx.x * blockDim.x + threadIdx.x;
    int lane = threadIdx.x & 31;
    int warp = tid >> 5;
    unsigned cb = (unsigned)warp * 256u;
    unsigned wb = (unsigned)warp * 8u;

    float fa[8];
    #pragma unroll
    for (int k = 0; k < 8; ++k) fa[k] = ini[cb + 32u * k + lane];

    unsigned myw = 0u;
    #pragma unroll
    for (int k = 0; k < 8; ++k) {
        unsigned bA = __ballot_sync(0xffffffffu, fa[k] > 0.5f);
        if (lane == k) myw = bA;
    }
    if (lane < 8) g_A[wb + lane] = myw;
}

// ---------------------------------------------------------------------------
// K2: role-split. Blocks [0,512): 8-generation bit-sliced life (g_A -> g_B).
// Blocks [512, 512+16384): target copy + pack (tgt -> out_tgt, g_T).
// Copy traffic (256 MB DRAM) hides the sim blocks' ALU time.
// ---------------------------------------------------------------------------
__device__ __forceinline__ void hsum(unsigned l, unsigned m, unsigned r,
                                     unsigned& h0, unsigned& h1) {
    unsigned L = __funnelshift_l(l, m, 1);
    unsigned R = __funnelshift_r(m, r, 1);
    unsigned t = L ^ R;
    h0 = t ^ m;
    h1 = (L & R) | (t & m);
}

__device__ __forceinline__ unsigned gol_combine(
    unsigned h0a, unsigned h1a, unsigned h0b, unsigned h1b,
    unsigned h0c, unsigned h1c, unsigned bm) {
    unsigned t  = h0a ^ h0b;
    unsigned s0 = t ^ h0c;
    unsigned c1 = (h0a & h0b) | (t & h0c);
    unsigned u  = h1a ^ h1b;
    unsigned p  = u ^ h1c;
    unsigned q  = (h1a & h1b) | (u & h1c);
    unsigned s1 = p ^ c1;
    unsigned c2 = p & c1;
    unsigned eq3 = s0 & s1 & ~(q | c2);
    unsigned eq4 = (q ^ c2) & ~(s0 | s1);
    return eq3 | (bm & eq4);
}

__global__ __launch_bounds__(256) void k_life_tgt(const float* __restrict__ tgt,
                                                  float* __restrict__ out_tgt) {
    int tid  = threadIdx.x;
    int lane = tid & 31;

    if (blockIdx.x >= SIMB) {
        // ---------------- target copy + pack role ----------------
        int cblk = blockIdx.x - SIMB;
        int warp = (cblk * 256 + tid) >> 5;
        unsigned cb = (unsigned)warp * 256u;
        unsigned wb = (unsigned)warp * 8u;

        float ft[8];
        #pragma unroll
        for (int k = 0; k < 8; ++k) ft[k] = tgt[cb + 32u * k + lane];
        #pragma unroll
        for (int k = 0; k < 8; ++k) out_tgt[cb + 32u * k + lane] = ft[k];

        unsigned myw = 0u;
        #pragma unroll
        for (int k = 0; k < 8; ++k) {
            unsigned bT = __ballot_sync(0xffffffffu, ft[k] > 0.5f);
            if (lane == k) myw = bT;
        }
        if (lane < 8) g_T[wb + lane] = myw;
        return;
    }

    // ---------------- life simulation role ----------------
    __shared__ unsigned sb[2][SH][SW];

    int tile = blockIdx.x;
    int b    = tile >> 4;
    int ty   = tile & 15;
    int r0   = ty * TH;

    const unsigned* img = g_A + b * WORDS_PER_IMG;

    for (int s = tid; s < SH; s += 256) {
        sb[0][s][0] = 0u; sb[0][s][33] = 0u;
        sb[1][s][0] = 0u; sb[1][s][33] = 0u;
    }
    for (int idx = tid; idx < SH * 32; idx += 256) {
        int s  = idx >> 5;
        int c  = idx & 31;
        int gr = r0 - 8 + s;
        unsigned v = ((unsigned)gr < (unsigned)HH) ? img[gr * WPR + c] : 0u;
        sb[0][s][c + 1] = v;
    }
    __syncthreads();

    int c      = tid & 31;
    int strip  = tid >> 5;
    int rstart = 1 + strip * 10;
    int rend   = (rstart + 10 < 79) ? (rstart + 10) : 79;

    #pragma unroll
    for (int g = 0; g < 8; ++g) {
        int cur = g & 1, nxt = cur ^ 1;

        unsigned h0a, h1a, h0b, h1b, h0c, h1c;
        hsum(sb[cur][rstart - 1][c], sb[cur][rstart - 1][c + 1], sb[cur][rstart - 1][c + 2], h0a, h1a);
        unsigned bm = sb[cur][rstart][c + 1];
        hsum(sb[cur][rstart][c], bm, sb[cur][rstart][c + 2], h0b, h1b);

        for (int r = rstart; r < rend; ++r) {
            unsigned nl = sb[cur][r + 1][c];
            unsigned nm = sb[cur][r + 1][c + 1];
            unsigned nr = sb[cur][r + 1][c + 2];
            hsum(nl, nm, nr, h0c, h1c);

            unsigned next = gol_combine(h0a, h1a, h0b, h1b, h0c, h1c, bm);
            if ((unsigned)(r0 - 8 + r) >= (unsigned)HH) next = 0u;
            sb[nxt][r][c + 1] = next;

            h0a = h0b; h1a = h1b;
            h0b = h0c; h1b = h1c;
            bm  = nm;
        }
        __syncthreads();
    }

    unsigned* dst = g_B + b * WORDS_PER_IMG;
    for (int idx = tid; idx < TH * 32; idx += 256) {
        int s  = idx >> 5;
        int cc = idx & 31;
        dst[(r0 + s) * WPR + cc] = sb[0][8 + s][cc + 1];
    }
}

// ---------------------------------------------------------------------------
// K3: unpack final bits -> state floats, word-level popc reduce, finalize.
// Warp handles 2x256 cells. Lanes 0-7 hold the words; shfl broadcast.
// ---------------------------------------------------------------------------
__global__ __launch_bounds__(256) void k_unpack_reduce(float* __restrict__ out) {
    __shared__ int sh_live[8], sh_mism[8];
    int tid  = threadIdx.x;
    int lane = tid & 31;
    int wrp  = tid >> 5;

    float* outs = out + 1;
    int live = 0, mism = 0;

    #pragma unroll
    for (int it = 0; it < 2; ++it) {
        int warp = (blockIdx.x * 8 + wrp) * 2 + it;
        unsigned cb = (unsigned)warp * 256u;
        unsigned wb = (unsigned)warp * 8u;

        unsigned w = 0u, t = 0u;
        if (lane < 8) { w = g_B[wb + lane]; t = g_T[wb + lane]; }
        live += __popc(w);
        mism += __popc(w ^ t);

        #pragma unroll
        for (int k = 0; k < 8; ++k) {
            unsigned wk = __shfl_sync(0xffffffffu, w, k);
            outs[cb + 32u * k + lane] =
                __uint_as_float(((wk >> lane) & 1u) * 0x3f800000u);
        }
    }

    #pragma unroll
    for (int o = 16; o > 0; o >>= 1) {
        live += __shfl_down_sync(0xffffffffu, live, o);
        mism += __shfl_down_sync(0xffffffffu, mism, o);
    }
    if (lane == 0) { sh_live[wrp] = live; sh_mism[wrp] = mism; }
    __syncthreads();
    if (tid == 0) {
        int L = 0, M = 0;
        #pragma unroll
        for (int k = 0; k < 8; ++k) { L += sh_live[k]; M += sh_mism[k]; }
        atomicAdd(&g_live, (unsigned long long)L);
        atomicAdd(&g_mism, (unsigned long long)M);
        __threadfence();
        unsigned prev = atomicAdd(&g_done, 1u);
        if (prev == (unsigned)(gridDim.x - 1)) {
            unsigned long long mt = atomicAdd(&g_mism, 0ull);
            unsigned long long lt = atomicAdd(&g_live, 0ull);
            out[0]              = (float)((double)mt / (double)NCELLS);  // loss
            out[1 + 2 * NCELLS] = (float)lt;                             // live_cells
            out[2 + 2 * NCELLS] = mt ? 1.0f : 0.0f;                      // max_abs_error
            g_live = 0ull; g_mism = 0ull;                                // replay reset
            __threadfence();
            g_done = 0u;
        }
    }
}

extern "C" void kernel_launch(void* const* d_in, const int* in_sizes, int n_in,
                              void* d_out, int out_size) {
    const float* initial = (const float*)d_in[0];
    const float* target  = (const float*)d_in[1];
    (void)in_sizes; (void)n_in; (void)out_size;   // generations fixed at 8

    float* out     = (float*)d_out;
    float* out_tgt = out + 1 + NCELLS;

    k_pack_ini<<<NCELLS / (8 * 256), 256>>>(initial);
    k_life_tgt<<<SIMB + NCELLS / (8 * 256), 256>>>(target, out_tgt);
    k_unpack_reduce<<<NCELLS / (2 * 8 * 256), 256>>>(out);
}